// round 14
// baseline (speedup 1.0000x reference)
#include <cuda_runtime.h>

// NCC2D: local normalized cross-correlation, 9x9 box, zero pad, scalar -mean(cc)
// Inputs: y_true, y_pred : [32,1,512,512] fp32. Output: 1 fp32.
//
// cross = IJ_sum - I_sum*J_sum/81 ; I_var = I2_sum - I_sum^2/81 (ditto J)
// cc = cross^2 / (I_var*J_var + 1e-5) ; out = -mean(cc)
//
// High-occupancy variant: block (4 warps) spans full 512-col strip; each lane
// owns 4 columns (20-reg accumulator). Halos: shuffle within warp, smem
// exchange (double-buffered, 1 barrier/row) across the 3 warp boundaries.

#define IMG_W 512
#define IMG_H 512
#define NBATCH 32
#define STRIP 8
#define NSTRIPS (IMG_H / STRIP)          // 64
#define NBLOCKS (NBATCH * NSTRIPS)       // 2048 blocks, 1 strip each
#define WPB 4                            // warps per block (4 x 128 cols)
#define NWARP (NBLOCKS * WPB)            // 8192 warp partials
#define OUTC 4

__device__ float g_partials[NWARP];
__device__ unsigned int g_counter;       // zero-init; reset by last block

// one field's horizontal sliding 9-sum over [Lhalo(4) | own(4) | Rhalo(4)]
__device__ __forceinline__ void field_wsum(const float (&v)[OUTC], int f,
                                           int lane, int w, int p,
                                           const float4 (&LP)[2][WPB][5],
                                           const float4 (&RP)[2][WPB][5],
                                           float (&ws)[OUTC]) {
    float L0 = __shfl_up_sync(0xffffffffu, v[0], 1);
    float L1 = __shfl_up_sync(0xffffffffu, v[1], 1);
    float L2 = __shfl_up_sync(0xffffffffu, v[2], 1);
    float L3 = __shfl_up_sync(0xffffffffu, v[3], 1);
    float R0 = __shfl_down_sync(0xffffffffu, v[0], 1);
    float R1 = __shfl_down_sync(0xffffffffu, v[1], 1);
    float R2 = __shfl_down_sync(0xffffffffu, v[2], 1);
    float R3 = __shfl_down_sync(0xffffffffu, v[3], 1);
    if (lane == 0) {
        float4 h = (w > 0) ? RP[p][w - 1][f] : make_float4(0.f, 0.f, 0.f, 0.f);
        L0 = h.x; L1 = h.y; L2 = h.z; L3 = h.w;
    }
    if (lane == 31) {
        float4 h = (w < WPB - 1) ? LP[p][w + 1][f] : make_float4(0.f, 0.f, 0.f, 0.f);
        R0 = h.x; R1 = h.y; R2 = h.z; R3 = h.w;
    }
    // window j in [k, k+8] over combined[12] = {L0..L3, v0..v3, R0..R3}
    float s = L0 + L1 + L2 + L3 + v[0] + v[1] + v[2] + v[3] + R0;
    ws[0] = s;
    s += R1 - L0; ws[1] = s;
    s += R2 - L1; ws[2] = s;
    s += R3 - L2; ws[3] = s;
}

__device__ __forceinline__ void vadd(float (&vI)[OUTC], float (&vJ)[OUTC],
                                     float (&vI2)[OUTC], float (&vJ2)[OUTC],
                                     float (&vIJ)[OUTC], float4 fi, float4 fj) {
    float ai[4] = {fi.x, fi.y, fi.z, fi.w};
    float aj[4] = {fj.x, fj.y, fj.z, fj.w};
#pragma unroll
    for (int q = 0; q < 4; q++) {
        float a = ai[q], c = aj[q];
        vI[q] += a; vJ[q] += c;
        vI2[q] = fmaf(a, a, vI2[q]);
        vJ2[q] = fmaf(c, c, vJ2[q]);
        vIJ[q] = fmaf(a, c, vIJ[q]);
    }
}

__device__ __forceinline__ void vsub(float (&vI)[OUTC], float (&vJ)[OUTC],
                                     float (&vI2)[OUTC], float (&vJ2)[OUTC],
                                     float (&vIJ)[OUTC], float4 fi, float4 fj) {
    float ai[4] = {fi.x, fi.y, fi.z, fi.w};
    float aj[4] = {fj.x, fj.y, fj.z, fj.w};
#pragma unroll
    for (int q = 0; q < 4; q++) {
        float a = ai[q], c = aj[q];
        vI[q] -= a; vJ[q] -= c;
        vI2[q] = fmaf(-a, a, vI2[q]);
        vJ2[q] = fmaf(-c, c, vJ2[q]);
        vIJ[q] = fmaf(-a, c, vIJ[q]);
    }
}

__global__ __launch_bounds__(WPB * 32, 6)
void ncc_main(const float* __restrict__ gI, const float* __restrict__ gJ,
              float* __restrict__ out) {
    __shared__ float4 LP[2][WPB][5];   // [parity][warp][field] lane0's v[0..3]
    __shared__ float4 RP[2][WPB][5];   // lane31's v[0..3]
    __shared__ bool is_last;
    __shared__ float sm[WPB * 32];

    const int w    = threadIdx.x >> 5;
    const int lane = threadIdx.x & 31;

    // block -> (batch, strip)
    const int b     = blockIdx.x >> 6;           // 64 strips per batch
    const int strip = blockIdx.x & (NSTRIPS - 1);
    const int r0 = strip * STRIP;
    const int col0 = w * 128 + lane * OUTC;      // in [0, 512)

    const float* __restrict__ Ib = gI + (size_t)b * (IMG_H * IMG_W) + col0;
    const float* __restrict__ Jb = gJ + (size_t)b * (IMG_H * IMG_W) + col0;

    float vI[OUTC], vJ[OUTC], vI2[OUTC], vJ2[OUTC], vIJ[OUTC];
#pragma unroll
    for (int q = 0; q < OUTC; q++)
        { vI[q] = vJ[q] = vI2[q] = vJ2[q] = vIJ[q] = 0.0f; }

    const int rlow = (r0 - 4 > 0) ? (r0 - 4) : 0;

    // warm-up rows [rlow, r0+4) — no barriers
    for (int rr = rlow; rr < r0 + 4; rr++) {
        float4 fi = *reinterpret_cast<const float4*>(Ib + rr * IMG_W);
        float4 fj = *reinterpret_cast<const float4*>(Jb + rr * IMG_W);
        vadd(vI, vJ, vI2, vJ2, vIJ, fi, fj);
    }

    const float s81 = 1.0f / 81.0f;
    float acc = 0.0f;

    for (int r = r0; r < r0 + STRIP; r++) {
        const int rin = r + 4;                 // block-uniform guards
        if (rin < IMG_H) {
            float4 fi = *reinterpret_cast<const float4*>(Ib + rin * IMG_W);
            float4 fj = *reinterpret_cast<const float4*>(Jb + rin * IMG_W);
            vadd(vI, vJ, vI2, vJ2, vIJ, fi, fj);
        }
        const int rout = r - 5;
        if (rout >= rlow) {
            float4 fi = *reinterpret_cast<const float4*>(Ib + rout * IMG_W);
            float4 fj = *reinterpret_cast<const float4*>(Jb + rout * IMG_W);
            vsub(vI, vJ, vI2, vJ2, vIJ, fi, fj);
        }

        const int p = r & 1;                   // double-buffered edge slots
        if (lane == 0) {
            LP[p][w][0] = make_float4(vI[0],  vI[1],  vI[2],  vI[3]);
            LP[p][w][1] = make_float4(vJ[0],  vJ[1],  vJ[2],  vJ[3]);
            LP[p][w][2] = make_float4(vI2[0], vI2[1], vI2[2], vI2[3]);
            LP[p][w][3] = make_float4(vJ2[0], vJ2[1], vJ2[2], vJ2[3]);
            LP[p][w][4] = make_float4(vIJ[0], vIJ[1], vIJ[2], vIJ[3]);
        } else if (lane == 31) {
            RP[p][w][0] = make_float4(vI[0],  vI[1],  vI[2],  vI[3]);
            RP[p][w][1] = make_float4(vJ[0],  vJ[1],  vJ[2],  vJ[3]);
            RP[p][w][2] = make_float4(vI2[0], vI2[1], vI2[2], vI2[3]);
            RP[p][w][3] = make_float4(vJ2[0], vJ2[1], vJ2[2], vJ2[3]);
            RP[p][w][4] = make_float4(vIJ[0], vIJ[1], vIJ[2], vIJ[3]);
        }
        __syncthreads();

        float wsI[OUTC], wsJ[OUTC], wsI2[OUTC], wsJ2[OUTC], wsIJ[OUTC];
        field_wsum(vI,  0, lane, w, p, LP, RP, wsI);
        field_wsum(vJ,  1, lane, w, p, LP, RP, wsJ);
        field_wsum(vI2, 2, lane, w, p, LP, RP, wsI2);
        field_wsum(vJ2, 3, lane, w, p, LP, RP, wsJ2);
        field_wsum(vIJ, 4, lane, w, p, LP, RP, wsIJ);

#pragma unroll
        for (int k = 0; k < OUTC; k++) {
            float t = wsI[k] * s81;
            float u = wsJ[k] * s81;
            float cross = fmaf(-t, wsJ[k], wsIJ[k]);
            float varI  = fmaf(-t, wsI[k], wsI2[k]);
            float varJ  = fmaf(-u, wsJ[k], wsJ2[k]);
            float denom = fmaf(varI, varJ, 1e-5f);
            acc += __fdividef(cross * cross, denom);
        }
    }

    // deterministic warp reduction -> per-warp partial
#pragma unroll
    for (int o = 16; o > 0; o >>= 1)
        acc += __shfl_down_sync(0xffffffffu, acc, o);
    if (lane == 0)
        g_partials[blockIdx.x * WPB + w] = acc;

    // fused final reduction: last finishing block sums all partials
    __syncthreads();
    if (threadIdx.x == 0) {
        __threadfence();
        unsigned int done = atomicAdd(&g_counter, 1u);
        is_last = (done == (unsigned int)(NBLOCKS - 1));
    }
    __syncthreads();
    if (!is_last) return;

    __threadfence();
    float v = 0.0f;
    for (int i = threadIdx.x; i < NWARP; i += WPB * 32)
        v += g_partials[i];
    sm[threadIdx.x] = v;
    __syncthreads();
#pragma unroll
    for (int stride = WPB * 16; stride > 0; stride >>= 1) {
        if (threadIdx.x < stride) sm[threadIdx.x] += sm[threadIdx.x + stride];
        __syncthreads();
    }
    if (threadIdx.x == 0) {
        out[0] = -sm[0] * (1.0f / (float)(NBATCH * IMG_H * IMG_W));
        g_counter = 0;
    }
}

extern "C" void kernel_launch(void* const* d_in, const int* in_sizes, int n_in,
                              void* d_out, int out_size) {
    const float* y_true = (const float*)d_in[0];
    const float* y_pred = (const float*)d_in[1];
    float* out = (float*)d_out;
    (void)in_sizes; (void)n_in; (void)out_size;

    ncc_main<<<NBLOCKS, WPB * 32>>>(y_true, y_pred, out);
}

// round 16
// speedup vs baseline: 1.2313x; 1.2313x over previous
#include <cuda_runtime.h>

// NCC2D: local normalized cross-correlation, 9x9 box, zero pad, scalar -mean(cc)
// Inputs: y_true, y_pred : [32,1,512,512] fp32. Output: 1 fp32.
//
// cross = IJ_sum - I_sum*J_sum/81 ; I_var = I2_sum - I_sum^2/81 (ditto J)
// cc = cross^2 / (I_var*J_var + 1e-5) ; out = -mean(cc)
//
// OUTC=8 hybrid: 2-warp block spans full 512-col strip (warp = 256 cols,
// lane = 8 cols, 40-reg accumulator). Halos via shuffle; single mid-row seam
// via 320B double-buffered smem exchange + 1 barrier/row.

#define IMG_W 512
#define IMG_H 512
#define NBATCH 32
#define STRIP 16
#define NSTRIPS (IMG_H / STRIP)          // 32
#define NBLOCKS (NBATCH * NSTRIPS)       // 1024 blocks
#define WPB 2                            // warps per block (2 x 256 cols)
#define THREADS (WPB * 32)               // 64
#define NWARP (NBLOCKS * WPB)            // 2048 warp partials
#define OUTC 8

__device__ float g_partials[NWARP];
__device__ unsigned int g_counter;       // zero-init; reset by last block

// combined window index i in [0,16): L[0..3] | v[0..7] | R[0..3]
#define CW(v, L, R, i) ((i) < 4 ? (L)[(i)] : ((i) < 12 ? (v)[(i)-4] : (R)[(i)-12]))

// one field: horizontal sliding 9-sum -> 8 window sums
__device__ __forceinline__ void field_wsum(const float (&v)[OUTC], int f,
                                           int lane, int w, int p,
                                           const float4 (&SL)[2][5],
                                           const float4 (&SR)[2][5],
                                           float (&ws)[OUTC]) {
    // left halo: prev lane's v[4..7]; at warp seam / image edge override
    float L[4], R[4];
    L[0] = __shfl_up_sync(0xffffffffu, v[4], 1);
    L[1] = __shfl_up_sync(0xffffffffu, v[5], 1);
    L[2] = __shfl_up_sync(0xffffffffu, v[6], 1);
    L[3] = __shfl_up_sync(0xffffffffu, v[7], 1);
    R[0] = __shfl_down_sync(0xffffffffu, v[0], 1);
    R[1] = __shfl_down_sync(0xffffffffu, v[1], 1);
    R[2] = __shfl_down_sync(0xffffffffu, v[2], 1);
    R[3] = __shfl_down_sync(0xffffffffu, v[3], 1);
    if (lane == 0) {
        // warp 1's left neighbor is warp 0's lane31 (SR); warp 0 -> image edge
        float4 h = (w == 1) ? SR[p][f] : make_float4(0.f, 0.f, 0.f, 0.f);
        L[0] = h.x; L[1] = h.y; L[2] = h.z; L[3] = h.w;
    }
    if (lane == 31) {
        // warp 0's right neighbor is warp 1's lane0 (SL); warp 1 -> image edge
        float4 h = (w == 0) ? SL[p][f] : make_float4(0.f, 0.f, 0.f, 0.f);
        R[0] = h.x; R[1] = h.y; R[2] = h.z; R[3] = h.w;
    }
    float s = L[0] + L[1] + L[2] + L[3] + v[0] + v[1] + v[2] + v[3] + v[4];
    ws[0] = s;
#pragma unroll
    for (int k = 1; k < OUTC; k++) {
        s += CW(v, L, R, k + 8) - CW(v, L, R, k - 1);
        ws[k] = s;
    }
}

// interleaved load+update for one image row (ADD or SUB)
template <bool ADD>
__device__ __forceinline__ void vrow(const float* __restrict__ Irow,
                                     const float* __restrict__ Jrow,
                                     float (&vI)[OUTC], float (&vJ)[OUTC],
                                     float (&vI2)[OUTC], float (&vJ2)[OUTC],
                                     float (&vIJ)[OUTC]) {
    const float4* pI = reinterpret_cast<const float4*>(Irow);
    const float4* pJ = reinterpret_cast<const float4*>(Jrow);
#pragma unroll
    for (int c = 0; c < 2; c++) {
        float4 fi = pI[c];
        float4 fj = pJ[c];
        float ai[4] = {fi.x, fi.y, fi.z, fi.w};
        float aj[4] = {fj.x, fj.y, fj.z, fj.w};
#pragma unroll
        for (int q = 0; q < 4; q++) {
            int j = c * 4 + q;
            float a = ai[q], cc = aj[q];
            if (ADD) {
                vI[j] += a; vJ[j] += cc;
                vI2[j] = fmaf(a, a, vI2[j]);
                vJ2[j] = fmaf(cc, cc, vJ2[j]);
                vIJ[j] = fmaf(a, cc, vIJ[j]);
            } else {
                vI[j] -= a; vJ[j] -= cc;
                vI2[j] = fmaf(-a, a, vI2[j]);
                vJ2[j] = fmaf(-cc, cc, vJ2[j]);
                vIJ[j] = fmaf(-a, cc, vIJ[j]);
            }
        }
    }
}

__global__ __launch_bounds__(THREADS, 10)
void ncc_main(const float* __restrict__ gI, const float* __restrict__ gJ,
              float* __restrict__ out) {
    __shared__ float4 SL[2][5];   // [parity][field]: warp1 lane0's v[0..3]
    __shared__ float4 SR[2][5];   // [parity][field]: warp0 lane31's v[4..7]
    __shared__ bool is_last;
    __shared__ float sm[THREADS];

    const int w    = threadIdx.x >> 5;
    const int lane = threadIdx.x & 31;

    const int b     = blockIdx.x >> 5;             // 32 strips per batch
    const int strip = blockIdx.x & (NSTRIPS - 1);
    const int r0 = strip * STRIP;
    const int col0 = w * 256 + lane * OUTC;        // in [0, 512)

    const float* __restrict__ Ib = gI + (size_t)b * (IMG_H * IMG_W) + col0;
    const float* __restrict__ Jb = gJ + (size_t)b * (IMG_H * IMG_W) + col0;

    float vI[OUTC], vJ[OUTC], vI2[OUTC], vJ2[OUTC], vIJ[OUTC];
#pragma unroll
    for (int q = 0; q < OUTC; q++)
        { vI[q] = vJ[q] = vI2[q] = vJ2[q] = vIJ[q] = 0.0f; }

    const int rlow = (r0 - 4 > 0) ? (r0 - 4) : 0;

    // warm-up rows [rlow, r0+4) — no barriers
    for (int rr = rlow; rr < r0 + 4; rr++)
        vrow<true>(Ib + rr * IMG_W, Jb + rr * IMG_W, vI, vJ, vI2, vJ2, vIJ);

    const float s81 = 1.0f / 81.0f;
    float acc = 0.0f;

    for (int r = r0; r < r0 + STRIP; r++) {
        const int rin = r + 4;                     // block-uniform guards
        if (rin < IMG_H)
            vrow<true>(Ib + rin * IMG_W, Jb + rin * IMG_W, vI, vJ, vI2, vJ2, vIJ);
        const int rout = r - 5;
        if (rout >= rlow)
            vrow<false>(Ib + rout * IMG_W, Jb + rout * IMG_W, vI, vJ, vI2, vJ2, vIJ);

        // seam exchange (double-buffered, one barrier per row)
        const int p = r & 1;
        if (w == 1 && lane == 0) {
            SL[p][0] = make_float4(vI[0],  vI[1],  vI[2],  vI[3]);
            SL[p][1] = make_float4(vJ[0],  vJ[1],  vJ[2],  vJ[3]);
            SL[p][2] = make_float4(vI2[0], vI2[1], vI2[2], vI2[3]);
            SL[p][3] = make_float4(vJ2[0], vJ2[1], vJ2[2], vJ2[3]);
            SL[p][4] = make_float4(vIJ[0], vIJ[1], vIJ[2], vIJ[3]);
        } else if (w == 0 && lane == 31) {
            SR[p][0] = make_float4(vI[4],  vI[5],  vI[6],  vI[7]);
            SR[p][1] = make_float4(vJ[4],  vJ[5],  vJ[6],  vJ[7]);
            SR[p][2] = make_float4(vI2[4], vI2[5], vI2[6], vI2[7]);
            SR[p][3] = make_float4(vJ2[4], vJ2[5], vJ2[6], vJ2[7]);
            SR[p][4] = make_float4(vIJ[4], vIJ[5], vIJ[6], vIJ[7]);
        }
        __syncthreads();

        float wsI[OUTC], wsJ[OUTC], wsI2[OUTC], wsJ2[OUTC], wsIJ[OUTC];
        field_wsum(vI,  0, lane, w, p, SL, SR, wsI);
        field_wsum(vJ,  1, lane, w, p, SL, SR, wsJ);
        field_wsum(vI2, 2, lane, w, p, SL, SR, wsI2);
        field_wsum(vJ2, 3, lane, w, p, SL, SR, wsJ2);
        field_wsum(vIJ, 4, lane, w, p, SL, SR, wsIJ);

#pragma unroll
        for (int k = 0; k < OUTC; k++) {
            float t = wsI[k] * s81;
            float u = wsJ[k] * s81;
            float cross = fmaf(-t, wsJ[k], wsIJ[k]);
            float varI  = fmaf(-t, wsI[k], wsI2[k]);
            float varJ  = fmaf(-u, wsJ[k], wsJ2[k]);
            float denom = fmaf(varI, varJ, 1e-5f);
            acc += __fdividef(cross * cross, denom);
        }
    }

    // deterministic warp reduction -> per-warp partial
#pragma unroll
    for (int o = 16; o > 0; o >>= 1)
        acc += __shfl_down_sync(0xffffffffu, acc, o);
    if (lane == 0)
        g_partials[blockIdx.x * WPB + w] = acc;

    // fused final reduction: last finishing block sums all partials
    __syncthreads();
    if (threadIdx.x == 0) {
        __threadfence();
        unsigned int done = atomicAdd(&g_counter, 1u);
        is_last = (done == (unsigned int)(NBLOCKS - 1));
    }
    __syncthreads();
    if (!is_last) return;

    __threadfence();
    float v = 0.0f;
    for (int i = threadIdx.x; i < NWARP; i += THREADS)
        v += g_partials[i];
    sm[threadIdx.x] = v;
    __syncthreads();
#pragma unroll
    for (int stride = THREADS / 2; stride > 0; stride >>= 1) {
        if (threadIdx.x < stride) sm[threadIdx.x] += sm[threadIdx.x + stride];
        __syncthreads();
    }
    if (threadIdx.x == 0) {
        out[0] = -sm[0] * (1.0f / (float)(NBATCH * IMG_H * IMG_W));
        g_counter = 0;
    }
}

extern "C" void kernel_launch(void* const* d_in, const int* in_sizes, int n_in,
                              void* d_out, int out_size) {
    const float* y_true = (const float*)d_in[0];
    const float* y_pred = (const float*)d_in[1];
    float* out = (float*)d_out;
    (void)in_sizes; (void)n_in; (void)out_size;

    ncc_main<<<NBLOCKS, THREADS>>>(y_true, y_pred, out);
}